// round 17
// baseline (speedup 1.0000x reference)
#include <cuda_runtime.h>
#include <math.h>

// Problem constants
#define BATCH 2
#define SEQ   2048
#define DMODEL 1024
#define NHEAD 16
#define DK    64
#define NBH   (BATCH*NHEAD)

// -------- scratch (no cudaMalloc allowed) --------
__device__ float g_Q[NBH * SEQ * DK];      // [b,h,s,d]
__device__ float g_K[NBH * SEQ * DK];
__device__ float g_V[NBH * SEQ * DK];
__device__ float g_attn[BATCH * SEQ * DMODEL]; // [b,s, h*dk]
__device__ float g_cos[SEQ * DK];
__device__ float g_sin[SEQ * DK];

// ============================================================
// Kernel 0: RoPE tables
// ============================================================
__global__ void rope_table_kernel(const int* __restrict__ tp) {
    int s = blockIdx.x;
    int d = threadIdx.x;
    int k = d >> 1;
    double freq = exp(-(double)(2 * k) / 64.0 * log(10000.0));
    double ang = (double)tp[s] * freq;
    g_cos[s * DK + d] = (float)cos(ang);
    g_sin[s * DK + d] = (float)sin(ang);
}

// ============================================================
// tf32 helpers
// ============================================================
__device__ __forceinline__ float tf32_rna(float x) {
    unsigned u;
    asm("cvt.rna.tf32.f32 %0, %1;" : "=r"(u) : "f"(x));
    return __uint_as_float(u);
}
// Truncation split: hi = tf32-prefix of x (LOP), lo = x - hi (exact FADD).
__device__ __forceinline__ void splitu(float x, unsigned& h, unsigned& l) {
    unsigned u = __float_as_uint(x) & 0xffffe000u;
    h = u;
    l = __float_as_uint(x - __uint_as_float(u));
}
__device__ __forceinline__ void mma_tf32(float c[4], const unsigned a[4], const unsigned b[2]) {
    asm volatile(
        "mma.sync.aligned.m16n8k8.row.col.f32.tf32.tf32.f32 "
        "{%0,%1,%2,%3}, {%4,%5,%6,%7}, {%8,%9}, {%0,%1,%2,%3};"
        : "+f"(c[0]), "+f"(c[1]), "+f"(c[2]), "+f"(c[3])
        : "r"(a[0]), "r"(a[1]), "r"(a[2]), "r"(a[3]), "r"(b[0]), "r"(b[1]));
}
__device__ __forceinline__ unsigned fu(float x) { return __float_as_uint(x); }

__device__ __forceinline__ void cp16(float* smem, const float* gmem) {
    unsigned saddr = (unsigned)__cvta_generic_to_shared(smem);
    asm volatile("cp.async.ca.shared.global [%0], [%1], 16;" :: "r"(saddr), "l"(gmem) : "memory");
}

// ---- GEMM smem layout: raw fp32, TRIPLE-buffered (validated round 11) ----
#define GS 20
#define SMA 0
#define SMB (128*GS)
#define BUFSZ (192*GS)
#define NSTAGE 3
#define SM_TOT (NSTAGE*BUFSZ)   // 46080 B

// ============================================================
// Pipelined GEMM mainloop (validated rounds 11-13)
// ============================================================
__device__ __forceinline__ void gemm_issue_copy(
    const float* __restrict__ Ap, const float* __restrict__ Bp,
    int kb, float* buf, int tid)
{
    const int r0 = tid >> 2;
    const int q0 = (tid & 3) * 4;
    cp16(buf + SMA + r0 * GS + q0, Ap + (size_t)r0 * DMODEL + kb + q0);
    cp16(buf + SMA + (r0 + 64) * GS + q0, Ap + (size_t)(r0 + 64) * DMODEL + kb + q0);
    cp16(buf + SMB + r0 * GS + q0, Bp + (size_t)r0 * DMODEL + kb + q0);
    asm volatile("cp.async.commit_group;" ::: "memory");
}

__device__ __forceinline__ void gemm_compute(
    const float* buf, float c[2][4][4], int wm, int wn, int lg, int lt)
{
    #pragma unroll
    for (int k0 = 0; k0 < 16; k0 += 8) {
        unsigned ah[2][4], al[2][4], bh[4][2], bl[4][2];
        #pragma unroll
        for (int mt = 0; mt < 2; mt++) {
            const int r = wm + mt * 16 + lg;
            splitu(buf[SMA + r * GS + k0 + lt],           ah[mt][0], al[mt][0]);
            splitu(buf[SMA + (r + 8) * GS + k0 + lt],     ah[mt][1], al[mt][1]);
            splitu(buf[SMA + r * GS + k0 + 4 + lt],       ah[mt][2], al[mt][2]);
            splitu(buf[SMA + (r + 8) * GS + k0 + 4 + lt], ah[mt][3], al[mt][3]);
        }
        #pragma unroll
        for (int nt = 0; nt < 4; nt++) {
            const int cc = wn + nt * 8 + lg;
            splitu(buf[SMB + cc * GS + k0 + lt],     bh[nt][0], bl[nt][0]);
            splitu(buf[SMB + cc * GS + k0 + 4 + lt], bh[nt][1], bl[nt][1]);
        }
        #pragma unroll
        for (int mt = 0; mt < 2; mt++)
            #pragma unroll
            for (int nt = 0; nt < 4; nt++) {
                mma_tf32(c[mt][nt], ah[mt], bh[nt]);
                mma_tf32(c[mt][nt], ah[mt], bl[nt]);
                mma_tf32(c[mt][nt], al[mt], bh[nt]);
            }
    }
}

__device__ __forceinline__ void mma_mainloop(
    const float* __restrict__ Ap, const float* __restrict__ Bp,
    float* sm, float c[2][4][4])
{
    const int tid = threadIdx.x;
    const int lane = tid & 31;
    const int wid = tid >> 5;
    const int wm = (wid & 3) * 32;
    const int wn = (wid >> 2) * 32;
    const int lg = lane >> 2;
    const int lt = lane & 3;
    const int NB = DMODEL / 16;

    gemm_issue_copy(Ap, Bp, 0, sm, tid);
    gemm_issue_copy(Ap, Bp, 16, sm + BUFSZ, tid);

    for (int i = 0; i < NB; i++) {
        if (i + 1 < NB)
            asm volatile("cp.async.wait_group 1;" ::: "memory");
        else
            asm volatile("cp.async.wait_group 0;" ::: "memory");
        __syncthreads();
        if (i + 2 < NB)
            gemm_issue_copy(Ap, Bp, (i + 2) * 16, sm + ((i + 2) % NSTAGE) * BUFSZ, tid);
        gemm_compute(sm + (i % NSTAGE) * BUFSZ, c, wm, wn, lg, lt);
    }
}

// ============================================================
// Kernel 1: QKV projection via 3xTF32 MMA (+RoPE epilogue)
// ============================================================
__global__ __launch_bounds__(256, 3) void qkv_mma_kernel(
    const float* __restrict__ x,
    const float* __restrict__ WQ,
    const float* __restrict__ WK,
    const float* __restrict__ WV)
{
    __shared__ float sm[SM_TOT];
    const int m0 = blockIdx.y * 128;
    const int e0 = blockIdx.x * 64;
    const int sect = e0 >> 10;
    const float* Wp = (sect == 0 ? WQ : (sect == 1 ? WK : WV)) + (size_t)(e0 & 1023) * DMODEL;
    const float* Ap = x + (size_t)m0 * DMODEL;

    float c[2][4][4] = {};
    mma_mainloop(Ap, Wp, sm, c);

    const int lane = threadIdx.x & 31;
    const int wid = threadIdx.x >> 5;
    const int wm = (wid & 3) * 32;
    const int wn = (wid >> 2) * 32;
    const int lg = lane >> 2, lt = lane & 3;
    float* dst = (sect == 0) ? g_Q : ((sect == 1) ? g_K : g_V);

    #pragma unroll
    for (int mt = 0; mt < 2; mt++) {
        #pragma unroll
        for (int nt = 0; nt < 4; nt++) {
            const int col = e0 + wn + nt * 8 + 2 * lt;
            const int ec = col & 1023;
            const int h = ec >> 6;
            const int d = ec & 63;
            #pragma unroll
            for (int half = 0; half < 2; half++) {
                const int row = m0 + wm + mt * 16 + lg + half * 8;
                const float v0 = c[mt][nt][half * 2 + 0];
                const float v1 = c[mt][nt][half * 2 + 1];
                const int b = row >> 11;
                const int srow = row & (SEQ - 1);
                const size_t oidx = (((size_t)(b * NHEAD + h)) * SEQ + srow) * DK + d;
                float2 o;
                if (sect < 2) {
                    const float cs = g_cos[srow * DK + d];
                    const float sn = g_sin[srow * DK + d];
                    o.x = v0 * cs - v1 * sn;
                    o.y = v1 * cs + v0 * sn;
                } else {
                    o.x = v0; o.y = v1;
                }
                *(float2*)(dst + oidx) = o;
            }
        }
    }
}

// ============================================================
// Kernel 3: output projection via 3xTF32 MMA
// ============================================================
__global__ __launch_bounds__(256, 3) void out_mma_kernel(
    const float* __restrict__ WO, float* __restrict__ out)
{
    __shared__ float sm[SM_TOT];
    const int m0 = blockIdx.y * 128;
    const int e0 = blockIdx.x * 64;
    const float* Ap = g_attn + (size_t)m0 * DMODEL;
    const float* Wp = WO + (size_t)e0 * DMODEL;

    float c[2][4][4] = {};
    mma_mainloop(Ap, Wp, sm, c);

    const int lane = threadIdx.x & 31;
    const int wid = threadIdx.x >> 5;
    const int wm = (wid & 3) * 32;
    const int wn = (wid >> 2) * 32;
    const int lg = lane >> 2, lt = lane & 3;

    #pragma unroll
    for (int mt = 0; mt < 2; mt++) {
        #pragma unroll
        for (int nt = 0; nt < 4; nt++) {
            const int col = e0 + wn + nt * 8 + 2 * lt;
            #pragma unroll
            for (int half = 0; half < 2; half++) {
                const int row = m0 + wm + mt * 16 + lg + half * 8;
                float2 o;
                o.x = c[mt][nt][half * 2 + 0];
                o.y = c[mt][nt][half * 2 + 1];
                *(float2*)(out + (size_t)row * DMODEL + col) = o;
            }
        }
    }
}

// ============================================================
// Kernel 2: causal flash attention (validated round 13; dynamic smem)
// ============================================================
#define KSTR 68
#define VSTR 72
#define PST  36
#define KVSTAGE (32*KSTR + 32*VSTR)
#define ATTN_SMEM_BYTES ((2*KVSTAGE + 64*PST) * 4)   // 45056 B

__global__ __launch_bounds__(128, 3) void attn_mma_kernel()
{
    extern __shared__ float smem[];
    float* s_ps = smem + 2 * KVSTAGE;

    const int qt = gridDim.x - 1 - blockIdx.x;
    const int bh = blockIdx.y;
    const int tid = threadIdx.x;
    const int w = tid >> 5;
    const int lane = tid & 31;
    const int lg = lane >> 2, lt = lane & 3;
    const int q0 = qt * 64;

    const float* Qb = g_Q + (size_t)bh * SEQ * DK;
    const float* Kb = g_K + (size_t)bh * SEQ * DK;
    const float* Vb = g_V + (size_t)bh * SEQ * DK;

    {
        const int row = tid & 63, half = tid >> 6;
        const float* src = Qb + (size_t)(q0 + row) * DK + 32 * half;
        float* dq = smem + row * KSTR + 32 * half;
        #pragma unroll
        for (int i = 0; i < 8; i++) {
            float4 v = *(const float4*)(src + 4 * i);
            v.x *= 0.125f; v.y *= 0.125f; v.z *= 0.125f; v.w *= 0.125f;
            *(float4*)(dq + 4 * i) = v;
        }
    }
    __syncthreads();

    unsigned qh[8][4], ql[8][4];
    {
        const int r0 = 16 * w + lg;
        #pragma unroll
        for (int kc = 0; kc < 8; kc++) {
            float f[4];
            f[0] = smem[r0 * KSTR + kc * 8 + lt];
            f[1] = smem[(r0 + 8) * KSTR + kc * 8 + lt];
            f[2] = smem[r0 * KSTR + kc * 8 + 4 + lt];
            f[3] = smem[(r0 + 8) * KSTR + kc * 8 + 4 + lt];
            #pragma unroll
            for (int i = 0; i < 4; i++) splitu(f[i], qh[kc][i], ql[kc][i]);
        }
    }
    __syncthreads();

    float o[8][4];
    #pragma unroll
    for (int nt = 0; nt < 8; nt++)
        #pragma unroll
        for (int i = 0; i < 4; i++) o[nt][i] = 0.f;
    float m0 = -1e30f, m1 = -1e30f, l0 = 0.f, l1 = 0.f;
    const int rg0 = q0 + 16 * w + lg;
    const int rg1 = rg0 + 8;
    const int nsub = 2 * qt + 2;

    {
        #pragma unroll
        for (int j = 0; j < 4; j++) {
            const int f = tid + j * 128;
            const int row = f >> 4, c4 = (f & 15) * 4;
            cp16(smem + row * KSTR + c4, Kb + (size_t)row * DK + c4);
            cp16(smem + 32 * KSTR + row * VSTR + c4, Vb + (size_t)row * DK + c4);
        }
        asm volatile("cp.async.commit_group;" ::: "memory");
    }

    for (int s32 = 0; s32 < nsub; s32++) {
        if (s32 + 1 < nsub) {
            const int k32n = (s32 + 1) * 32;
            float* buf = smem + ((s32 + 1) & 1) * KVSTAGE;
            #pragma unroll
            for (int j = 0; j < 4; j++) {
                const int f = tid + j * 128;
                const int row = f >> 4, c4 = (f & 15) * 4;
                cp16(buf + row * KSTR + c4, Kb + (size_t)(k32n + row) * DK + c4);
                cp16(buf + 32 * KSTR + row * VSTR + c4, Vb + (size_t)(k32n + row) * DK + c4);
            }
            asm volatile("cp.async.commit_group;" ::: "memory");
            asm volatile("cp.async.wait_group 1;" ::: "memory");
        } else {
            asm volatile("cp.async.wait_group 0;" ::: "memory");
        }
        __syncthreads();

        const int k32 = s32 * 32;
        const float* kb = smem + (s32 & 1) * KVSTAGE;
        const float* vb = kb + 32 * KSTR;
        const bool active = (k32 <= q0 + 16 * w + 15);
        if (active) {
            float s[4][4];
            #pragma unroll
            for (int nt = 0; nt < 4; nt++)
                #pragma unroll
                for (int i = 0; i < 4; i++) s[nt][i] = 0.f;
            #pragma unroll
            for (int nt = 0; nt < 4; nt++) {
                const int kr = (nt * 8 + lg) * KSTR;
                #pragma unroll
                for (int kc = 0; kc < 8; kc++) {
                    unsigned bhf[2], blf[2];
                    splitu(kb[kr + kc * 8 + lt],     bhf[0], blf[0]);
                    splitu(kb[kr + kc * 8 + 4 + lt], bhf[1], blf[1]);
                    mma_tf32(s[nt], qh[kc], bhf);
                    mma_tf32(s[nt], ql[kc], bhf);
                    mma_tf32(s[nt], qh[kc], blf);
                }
            }
            if (k32 + 31 > rg0) {
                #pragma unroll
                for (int nt = 0; nt < 4; nt++) {
                    const int j = k32 + nt * 8 + 2 * lt;
                    if (j > rg0)     s[nt][0] = -1e30f;
                    if (j + 1 > rg0) s[nt][1] = -1e30f;
                }
            }
            if (k32 + 31 > rg1) {
                #pragma unroll
                for (int nt = 0; nt < 4; nt++) {
                    const int j = k32 + nt * 8 + 2 * lt;
                    if (j > rg1)     s[nt][2] = -1e30f;
                    if (j + 1 > rg1) s[nt][3] = -1e30f;
                }
            }
            float mt0 = -1e30f, mt1 = -1e30f;
            #pragma unroll
            for (int nt = 0; nt < 4; nt++) {
                mt0 = fmaxf(mt0, fmaxf(s[nt][0], s[nt][1]));
                mt1 = fmaxf(mt1, fmaxf(s[nt][2], s[nt][3]));
            }
            mt0 = fmaxf(mt0, __shfl_xor_sync(0xffffffffu, mt0, 1));
            mt0 = fmaxf(mt0, __shfl_xor_sync(0xffffffffu, mt0, 2));
            mt1 = fmaxf(mt1, __shfl_xor_sync(0xffffffffu, mt1, 1));
            mt1 = fmaxf(mt1, __shfl_xor_sync(0xffffffffu, mt1, 2));
            const float mn0 = fmaxf(m0, mt0), mn1 = fmaxf(m1, mt1);
            const float a0 = __expf(m0 - mn0), a1 = __expf(m1 - mn1);
            m0 = mn0; m1 = mn1;
            float sum0 = 0.f, sum1 = 0.f;
            #pragma unroll
            for (int nt = 0; nt < 4; nt++) {
                s[nt][0] = __expf(s[nt][0] - mn0);
                s[nt][1] = __expf(s[nt][1] - mn0);
                s[nt][2] = __expf(s[nt][2] - mn1);
                s[nt][3] = __expf(s[nt][3] - mn1);
                sum0 += s[nt][0] + s[nt][1];
                sum1 += s[nt][2] + s[nt][3];
            }
            sum0 += __shfl_xor_sync(0xffffffffu, sum0, 1);
            sum0 += __shfl_xor_sync(0xffffffffu, sum0, 2);
            sum1 += __shfl_xor_sync(0xffffffffu, sum1, 1);
            sum1 += __shfl_xor_sync(0xffffffffu, sum1, 2);
            l0 = l0 * a0 + sum0;
            l1 = l1 * a1 + sum1;
            #pragma unroll
            for (int nt = 0; nt < 8; nt++) {
                o[nt][0] *= a0; o[nt][1] *= a0;
                o[nt][2] *= a1; o[nt][3] *= a1;
            }
            {
                const int pr0 = (16 * w + lg) * PST;
                const int pr1 = (16 * w + 8 + lg) * PST;
                #pragma unroll
                for (int nt = 0; nt < 4; nt++) {
                    float2 p01 = make_float2(tf32_rna(s[nt][0]), tf32_rna(s[nt][1]));
                    float2 p23 = make_float2(tf32_rna(s[nt][2]), tf32_rna(s[nt][3]));
                    *(float2*)(s_ps + pr0 + nt * 8 + 2 * lt) = p01;
                    *(float2*)(s_ps + pr1 + nt * 8 + 2 * lt) = p23;
                }
            }
            __syncwarp();
            unsigned pa[4][4];
            #pragma unroll
            for (int kc = 0; kc < 4; kc++) {
                pa[kc][0] = fu(s_ps[(16 * w + lg) * PST + kc * 8 + lt]);
                pa[kc][1] = fu(s_ps[(16 * w + 8 + lg) * PST + kc * 8 + lt]);
                pa[kc][2] = fu(s_ps[(16 * w + lg) * PST + kc * 8 + 4 + lt]);
                pa[kc][3] = fu(s_ps[(16 * w + 8 + lg) * PST + kc * 8 + 4 + lt]);
            }
            #pragma unroll
            for (int nt = 0; nt < 8; nt++) {
                #pragma unroll
                for (int kc = 0; kc < 4; kc++) {
                    unsigned vbf[2];
                    vbf[0] = fu(vb[(kc * 8 + lt) * VSTR + nt * 8 + lg]);
                    vbf[1] = fu(vb[(kc * 8 + 4 + lt) * VSTR + nt * 8 + lg]);
                    mma_tf32(o[nt], pa[kc], vbf);
                }
            }
        }
        __syncthreads();
    }

    const float inv0 = 1.0f / l0, inv1 = 1.0f / l1;
    const int b = bh >> 4, h = bh & 15;
    float* dst0 = g_attn + ((size_t)b * SEQ + rg0) * DMODEL + h * DK;
    float* dst1 = g_attn + ((size_t)b * SEQ + rg1) * DMODEL + h * DK;
    #pragma unroll
    for (int nt = 0; nt < 8; nt++) {
        *(float2*)(dst0 + nt * 8 + 2 * lt) = make_float2(o[nt][0] * inv0, o[nt][1] * inv0);
        *(float2*)(dst1 + nt * 8 + 2 * lt) = make_float2(o[nt][2] * inv1, o[nt][3] * inv1);
    }
}

// ============================================================
extern "C" void kernel_launch(void* const* d_in, const int* in_sizes, int n_in,
                              void* d_out, int out_size)
{
    const float* x  = (const float*)d_in[0];
    const float* WQ = (const float*)d_in[1];
    const float* WK = (const float*)d_in[2];
    const float* WV = (const float*)d_in[3];
    const float* WO = (const float*)d_in[4];
    const int*   tp = (const int*)d_in[5];
    float* out = (float*)d_out;

    // Opt-in dynamic smem for attention (idempotent; host-side attribute,
    // not a stream op -> graph-capture safe).
    cudaFuncSetAttribute(attn_mma_kernel,
                         cudaFuncAttributeMaxDynamicSharedMemorySize,
                         ATTN_SMEM_BYTES);

    rope_table_kernel<<<SEQ, DK>>>(tp);
    qkv_mma_kernel<<<dim3(3 * DMODEL / 64, BATCH * SEQ / 128), 256>>>(x, WQ, WK, WV);
    attn_mma_kernel<<<dim3(SEQ / 64, NBH), 128, ATTN_SMEM_BYTES>>>();
    out_mma_kernel<<<dim3(DMODEL / 64, BATCH * SEQ / 128), 256>>>(WO, out);
}